// round 6
// baseline (speedup 1.0000x reference)
#include <cuda_runtime.h>
#include <math.h>

#define T_TOKENS 8192
#define DMODEL   1024
#define HDIM     4096
#define NEXP     8
#define NPAIR    16384   // T_TOKENS * TOP_K

// ---------------- scratch (device globals: no allocation allowed) ------------
// g_h holds ONE expert's hidden activations at a time (max 8192 rows): 128 MB.
// Correct because GEMM1(e) -> GEMM2(e) are chained per expert on one stream.
__device__ float g_h[(size_t)T_TOKENS * HDIM];
__device__ int   g_topk_idx[T_TOKENS * 2];
__device__ float g_topk_w[T_TOKENS * 2];
__device__ int   g_cnt[NEXP];
__device__ int   g_off[NEXP + 1];
__device__ int   g_cur[NEXP];
__device__ int   g_rows[NPAIR];    // pair slot -> token id (expert-sorted)
__device__ float g_wpair[NPAIR];   // pair slot -> gate weight

// ---------------- small kernels ---------------------------------------------
__global__ void zero_kernel() {
    int i = threadIdx.x;
    if (i < NEXP) { g_cnt[i] = 0; g_cur[i] = 0; }
}

__global__ void zero_out_kernel(float* __restrict__ out) {
    ((float4*)out)[(size_t)blockIdx.x * blockDim.x + threadIdx.x] =
        make_float4(0.f, 0.f, 0.f, 0.f);
}

// One warp per token: logits over 8 experts, top-2, softmax.
__global__ void router_kernel(const float* __restrict__ x,
                              const float* __restrict__ semb,
                              const float* __restrict__ rw,
                              const float* __restrict__ rb,
                              const int*   __restrict__ sidx) {
    int gw   = (blockIdx.x * blockDim.x + threadIdx.x) >> 5;
    int lane = threadIdx.x & 31;
    if (gw >= T_TOKENS) return;
    const float* xr = x + (size_t)gw * DMODEL;
    const float* er = semb + (size_t)(*sidx) * DMODEL;
    float acc[NEXP];
#pragma unroll
    for (int e = 0; e < NEXP; e++) acc[e] = 0.f;
    for (int d = lane; d < DMODEL; d += 32) {
        float v = xr[d] + er[d];
#pragma unroll
        for (int e = 0; e < NEXP; e++) acc[e] += v * rw[e * DMODEL + d];
    }
#pragma unroll
    for (int e = 0; e < NEXP; e++) {
#pragma unroll
        for (int o = 16; o > 0; o >>= 1)
            acc[e] += __shfl_xor_sync(0xffffffffu, acc[e], o);
    }
    if (lane == 0) {
        float b0 = -1e30f, b1 = -1e30f; int i0 = 0, i1 = 0;
#pragma unroll
        for (int e = 0; e < NEXP; e++) {
            float l = acc[e] + rb[e];
            if (l > b0)      { b1 = b0; i1 = i0; b0 = l; i0 = e; }
            else if (l > b1) { b1 = l;  i1 = e; }
        }
        float w0 = 1.f / (1.f + expf(b1 - b0));
        float w1 = 1.f - w0;
        g_topk_idx[2 * gw]     = i0;
        g_topk_idx[2 * gw + 1] = i1;
        g_topk_w[2 * gw]       = w0;
        g_topk_w[2 * gw + 1]   = w1;
        atomicAdd(&g_cnt[i0], 1);
        atomicAdd(&g_cnt[i1], 1);
    }
}

__global__ void scan_kernel() {
    if (threadIdx.x == 0) {
        int s = 0;
        for (int e = 0; e < NEXP; e++) { g_off[e] = s; g_cur[e] = s; s += g_cnt[e]; }
        g_off[NEXP] = s;
    }
}

__global__ void build_kernel() {
    int t = blockIdx.x * blockDim.x + threadIdx.x;
    if (t >= T_TOKENS) return;
#pragma unroll
    for (int k = 0; k < 2; k++) {
        int e = g_topk_idx[2 * t + k];
        int p = atomicAdd(&g_cur[e], 1);
        g_rows[p]  = t;
        g_wpair[p] = g_topk_w[2 * t + k];
    }
}

// ---------------- grouped GEMM (one expert per launch) -----------------------
// GEMM1 (GATHER=true,  GELU=true):  g_h[r-off] = gelu(x[g_rows[r]] @ W1[e]^T + b1[e])
// GEMM2 (GATHER=false, GELU=false): out[g_rows[r]] += g_wpair[r] *
//                                   (g_h[r-off] @ W2[e]^T + b2[e])   via atomicAdd
template <bool GATHER, bool GELU>
__global__ __launch_bounds__(256, 2)
void moe_gemm(const float* __restrict__ Abase,
              const float* __restrict__ Ball,
              const float* __restrict__ biasAll,
              float* __restrict__ out,
              int K, int N, int e) {
    const int BM = 128, BN = 128, BK = 16;
    int off0 = g_off[e];
    int seg1 = g_off[e + 1];
    int r0   = off0 + blockIdx.y * BM;
    if (r0 >= seg1) return;
    int n0 = blockIdx.x * BN;

    const float* Asrc = GATHER ? Abase : (const float*)g_h;

    __shared__ float As[2][BK][BM];
    __shared__ float Bs[2][BK][BN];

    int tid  = threadIdx.x;
    int lrow = tid >> 2;            // 0..63
    int lkq  = (tid & 3) * 4;       // 0,4,8,12

    const float* aptr[2];
    bool avalid[2];
#pragma unroll
    for (int i = 0; i < 2; i++) {
        int r = r0 + lrow + i * 64;
        avalid[i] = (r < seg1);
        int src = 0;
        if (avalid[i]) src = GATHER ? g_rows[r] : (r - off0);
        aptr[i] = Asrc + (size_t)src * K + lkq;
    }
    const float* Bexp = Ball + (size_t)e * N * K;
    const float* bptr[2];
#pragma unroll
    for (int i = 0; i < 2; i++)
        bptr[i] = Bexp + (size_t)(n0 + lrow + i * 64) * K + lkq;

    int ty = tid >> 4, tx = tid & 15;

    float acc[8][8];
#pragma unroll
    for (int i = 0; i < 8; i++)
#pragma unroll
        for (int j = 0; j < 8; j++) acc[i][j] = 0.f;

    float4 aT[2], bT[2];
#pragma unroll
    for (int i = 0; i < 2; i++) {
        aT[i] = avalid[i] ? *(const float4*)(aptr[i]) : make_float4(0.f, 0.f, 0.f, 0.f);
        bT[i] = *(const float4*)(bptr[i]);
    }
#pragma unroll
    for (int i = 0; i < 2; i++) {
        int m = lrow + i * 64;
        As[0][lkq + 0][m] = aT[i].x; As[0][lkq + 1][m] = aT[i].y;
        As[0][lkq + 2][m] = aT[i].z; As[0][lkq + 3][m] = aT[i].w;
        Bs[0][lkq + 0][m] = bT[i].x; Bs[0][lkq + 1][m] = bT[i].y;
        Bs[0][lkq + 2][m] = bT[i].z; Bs[0][lkq + 3][m] = bT[i].w;
    }
    __syncthreads();

    int buf = 0;
    int KT  = K / BK;
    for (int kt = 0; kt < KT; kt++) {
        if (kt + 1 < KT) {
            int koff = (kt + 1) * BK;
#pragma unroll
            for (int i = 0; i < 2; i++) {
                aT[i] = avalid[i] ? *(const float4*)(aptr[i] + koff)
                                  : make_float4(0.f, 0.f, 0.f, 0.f);
                bT[i] = *(const float4*)(bptr[i] + koff);
            }
        }
#pragma unroll
        for (int k = 0; k < BK; k++) {
            float4 a0 = *(const float4*)&As[buf][k][ty * 8];
            float4 a1 = *(const float4*)&As[buf][k][ty * 8 + 4];
            float4 b0 = *(const float4*)&Bs[buf][k][tx * 8];
            float4 b1 = *(const float4*)&Bs[buf][k][tx * 8 + 4];
            float ar[8] = {a0.x, a0.y, a0.z, a0.w, a1.x, a1.y, a1.z, a1.w};
            float br[8] = {b0.x, b0.y, b0.z, b0.w, b1.x, b1.y, b1.z, b1.w};
#pragma unroll
            for (int i = 0; i < 8; i++)
#pragma unroll
                for (int j = 0; j < 8; j++)
                    acc[i][j] += ar[i] * br[j];
        }
        if (kt + 1 < KT) {
            int nb = buf ^ 1;
#pragma unroll
            for (int i = 0; i < 2; i++) {
                int m = lrow + i * 64;
                As[nb][lkq + 0][m] = aT[i].x; As[nb][lkq + 1][m] = aT[i].y;
                As[nb][lkq + 2][m] = aT[i].z; As[nb][lkq + 3][m] = aT[i].w;
                Bs[nb][lkq + 0][m] = bT[i].x; Bs[nb][lkq + 1][m] = bT[i].y;
                Bs[nb][lkq + 2][m] = bT[i].z; Bs[nb][lkq + 3][m] = bT[i].w;
            }
            __syncthreads();
            buf = nb;
        }
    }

    const float* bias = biasAll + (size_t)e * N;
#pragma unroll
    for (int i = 0; i < 8; i++) {
        int r = r0 + ty * 8 + i;
        if (r < seg1) {
            if (GELU) {
                // write hidden activations (expert-relative) with tanh-gelu
                float* crow = g_h + (size_t)(r - off0) * N + n0 + tx * 8;
                float vr[8];
#pragma unroll
                for (int j = 0; j < 8; j++) {
                    float u = acc[i][j] + bias[n0 + tx * 8 + j];
                    float c = 0.7978845608028654f * (u + 0.044715f * u * u * u);
                    vr[j] = 0.5f * u * (1.f + tanhf(c));
                }
                *(float4*)(crow)     = make_float4(vr[0], vr[1], vr[2], vr[3]);
                *(float4*)(crow + 4) = make_float4(vr[4], vr[5], vr[6], vr[7]);
            } else {
                // scaled atomic accumulate into the final output
                int   t = g_rows[r];
                float w = g_wpair[r];
                float* orow = out + (size_t)t * N + n0 + tx * 8;
#pragma unroll
                for (int j = 0; j < 8; j++)
                    atomicAdd(orow + j, w * (acc[i][j] + bias[n0 + tx * 8 + j]));
            }
        }
    }
}

// ---------------- launch -----------------------------------------------------
extern "C" void kernel_launch(void* const* d_in, const int* in_sizes, int n_in,
                              void* d_out, int out_size) {
    const float* x    = (const float*)d_in[0];
    const float* semb = (const float*)d_in[1];
    const float* rw   = (const float*)d_in[2];
    const float* rb   = (const float*)d_in[3];
    const float* w1   = (const float*)d_in[4];
    const float* b1   = (const float*)d_in[5];
    const float* w2   = (const float*)d_in[6];
    const float* b2   = (const float*)d_in[7];
    const int*   sidx = (const int*)d_in[8];
    float* out = (float*)d_out;

    zero_kernel<<<1, 32>>>();
    zero_out_kernel<<<(T_TOKENS * DMODEL / 4) / 256, 256>>>(out);
    router_kernel<<<T_TOKENS / 8, 256>>>(x, semb, rw, rb, sidx);
    scan_kernel<<<1, 32>>>();
    build_kernel<<<T_TOKENS / 256, 256>>>();

    // Per-expert chained GEMMs: g_h is reused across experts, so GEMM1(e) and
    // GEMM2(e) must complete before GEMM1(e+1). Stream order guarantees this.
    for (int e = 0; e < NEXP; e++) {
        dim3 g1(HDIM / 128, 64);   // hidden = gelu(x @ W1^T + b1)  (K=1024, N=4096)
        moe_gemm<true,  true ><<<g1, 256>>>(x, w1, b1, out, DMODEL, HDIM, e);
        dim3 g2(DMODEL / 128, 64); // out += w * (h @ W2^T + b2)    (K=4096, N=1024)
        moe_gemm<false, false><<<g2, 256>>>(x, w2, b2, out, HDIM, DMODEL, e);
    }
}

// round 11
// speedup vs baseline: 2.7126x; 2.7126x over previous
#include <cuda_runtime.h>
#include <cuda_bf16.h>
#include <math.h>
#include <stdint.h>

#define T_TOKENS 8192
#define DMODEL   1024
#define HDIM     4096
#define NEXP     8
#define NPAIR    16384   // T_TOKENS * TOP_K

// ---------------- scratch (device globals: no allocation allowed) ------------
// g_h holds ONE expert's hidden activations at a time (max 8192 rows): 128 MB.
__device__ float g_h[(size_t)T_TOKENS * HDIM];
__device__ int   g_topk_idx[T_TOKENS * 2];
__device__ float g_topk_w[T_TOKENS * 2];
__device__ int   g_cnt[NEXP];
__device__ int   g_off[NEXP + 1];
__device__ int   g_cur[NEXP];
__device__ int   g_rows[NPAIR];    // pair slot -> token id (expert-sorted)
__device__ float g_wpair[NPAIR];   // pair slot -> gate weight

// ---------------- helpers ----------------------------------------------------
__device__ __forceinline__ uint32_t smem_u32(const void* p) {
    uint32_t a;
    asm("{ .reg .u64 t; cvta.to.shared.u64 t, %1; cvt.u32.u64 %0, t; }"
        : "=r"(a) : "l"(p));
    return a;
}
#define LDMX4(r0, r1, r2, r3, addr) \
    asm volatile("ldmatrix.sync.aligned.m8n8.x4.shared.b16 {%0,%1,%2,%3}, [%4];" \
                 : "=r"(r0), "=r"(r1), "=r"(r2), "=r"(r3) : "r"(addr))

__device__ __forceinline__ void mma16816(float* c, const uint32_t* a,
                                         const uint32_t* b) {
    asm volatile(
        "mma.sync.aligned.m16n8k16.row.col.f32.bf16.bf16.f32 "
        "{%0,%1,%2,%3}, {%4,%5,%6,%7}, {%8,%9}, {%0,%1,%2,%3};"
        : "+f"(c[0]), "+f"(c[1]), "+f"(c[2]), "+f"(c[3])
        : "r"(a[0]), "r"(a[1]), "r"(a[2]), "r"(a[3]), "r"(b[0]), "r"(b[1]));
}

// ---------------- small kernels ---------------------------------------------
__global__ void zero_kernel() {
    int i = threadIdx.x;
    if (i < NEXP) { g_cnt[i] = 0; g_cur[i] = 0; }
}
__global__ void zero_out_kernel(float* __restrict__ out) {
    ((float4*)out)[(size_t)blockIdx.x * blockDim.x + threadIdx.x] =
        make_float4(0.f, 0.f, 0.f, 0.f);
}

__global__ void router_kernel(const float* __restrict__ x,
                              const float* __restrict__ semb,
                              const float* __restrict__ rw,
                              const float* __restrict__ rb,
                              const int*   __restrict__ sidx) {
    int gw   = (blockIdx.x * blockDim.x + threadIdx.x) >> 5;
    int lane = threadIdx.x & 31;
    if (gw >= T_TOKENS) return;
    const float* xr = x + (size_t)gw * DMODEL;
    const float* er = semb + (size_t)(*sidx) * DMODEL;
    float acc[NEXP];
#pragma unroll
    for (int e = 0; e < NEXP; e++) acc[e] = 0.f;
    for (int d = lane; d < DMODEL; d += 32) {
        float v = xr[d] + er[d];
#pragma unroll
        for (int e = 0; e < NEXP; e++) acc[e] += v * rw[e * DMODEL + d];
    }
#pragma unroll
    for (int e = 0; e < NEXP; e++) {
#pragma unroll
        for (int o = 16; o > 0; o >>= 1)
            acc[e] += __shfl_xor_sync(0xffffffffu, acc[e], o);
    }
    if (lane == 0) {
        float b0 = -1e30f, b1 = -1e30f; int i0 = 0, i1 = 0;
#pragma unroll
        for (int e = 0; e < NEXP; e++) {
            float l = acc[e] + rb[e];
            if (l > b0)      { b1 = b0; i1 = i0; b0 = l; i0 = e; }
            else if (l > b1) { b1 = l;  i1 = e; }
        }
        float w0 = 1.f / (1.f + expf(b1 - b0));
        float w1 = 1.f - w0;
        g_topk_idx[2 * gw]     = i0;
        g_topk_idx[2 * gw + 1] = i1;
        g_topk_w[2 * gw]       = w0;
        g_topk_w[2 * gw + 1]   = w1;
        atomicAdd(&g_cnt[i0], 1);
        atomicAdd(&g_cnt[i1], 1);
    }
}

__global__ void scan_kernel() {
    if (threadIdx.x == 0) {
        int s = 0;
        for (int e = 0; e < NEXP; e++) { g_off[e] = s; g_cur[e] = s; s += g_cnt[e]; }
        g_off[NEXP] = s;
    }
}

__global__ void build_kernel() {
    int t = blockIdx.x * blockDim.x + threadIdx.x;
    if (t >= T_TOKENS) return;
#pragma unroll
    for (int k = 0; k < 2; k++) {
        int e = g_topk_idx[2 * t + k];
        int p = atomicAdd(&g_cur[e], 1);
        g_rows[p]  = t;
        g_wpair[p] = g_topk_w[2 * t + k];
    }
}

// ---------------- HMMA grouped GEMM (one expert per launch) -------------------
// fp32 emulated via bf16 2-term split: a = ah+al; a*b ~= ah*bh + ah*bl + al*bh.
// Tile M=128, N=128, BK=32 bf16; 8 warps (4 M x 2 N), warp tile 32x64.
// mma.sync.m16n8k16 (family-target legal; no tcgen05).
// SMEM rows padded to 40 halves (80 B) -> conflict-free ldmatrix.
#define KPAD 40

template <bool GATHER, bool GELU>
__global__ __launch_bounds__(256, 2)
void moe_gemm_mma(const float* __restrict__ Abase,
                  const float* __restrict__ Ball,
                  const float* __restrict__ biasAll,
                  float* __restrict__ out,
                  int K, int N, int e) {
    int off0 = g_off[e];
    int seg1 = g_off[e + 1];
    int r0   = off0 + blockIdx.y * 128;
    if (r0 >= seg1) return;
    int n0 = blockIdx.x * 128;

    __shared__ __nv_bfloat16 sA[2][128][KPAD];   // [hi/lo][m][k]
    __shared__ __nv_bfloat16 sB[2][128][KPAD];   // [hi/lo][n][k]

    int tid  = threadIdx.x;
    int wid  = tid >> 5;
    int lane = tid & 31;
    int mbase = (wid & 3) * 32;   // warp M offset in tile
    int nbase = (wid >> 2) * 64;  // warp N offset in tile

    const float* Asrc = GATHER ? Abase : (const float*)g_h;
    const float* Bexp = Ball + (size_t)e * N * K;

    float C[2][8][4];
#pragma unroll
    for (int mt = 0; mt < 2; mt++)
#pragma unroll
        for (int nt = 0; nt < 8; nt++)
#pragma unroll
            for (int q = 0; q < 4; q++) C[mt][nt][q] = 0.f;

    // precompute this thread's fill coordinates (4 float4 each for A and B)
    const int KT = K >> 5;   // BK = 32

    for (int kt = 0; kt < KT; kt++) {
        int k0 = kt * 32;
        __syncthreads();   // previous iteration's MMA reads complete

        // ---- fill: 128 rows x 32 k fp32 for A and B, split hi/lo -------------
#pragma unroll
        for (int i = 0; i < 4; i++) {
            int q   = tid + i * 256;       // 0..1023
            int row = q >> 3;              // 0..127
            int kq  = (q & 7) * 4;         // 0,4,...,28

            float4 av = make_float4(0.f, 0.f, 0.f, 0.f);
            int r = r0 + row;
            if (r < seg1) {
                int src = GATHER ? g_rows[r] : (r - off0);
                av = *(const float4*)(Asrc + (size_t)src * K + k0 + kq);
            }
            __nv_bfloat162 ah01 = __floats2bfloat162_rn(av.x, av.y);
            __nv_bfloat162 ah23 = __floats2bfloat162_rn(av.z, av.w);
            float2 f01 = __bfloat1622float2(ah01);
            float2 f23 = __bfloat1622float2(ah23);
            __nv_bfloat162 al01 = __floats2bfloat162_rn(av.x - f01.x, av.y - f01.y);
            __nv_bfloat162 al23 = __floats2bfloat162_rn(av.z - f23.x, av.w - f23.y);
            *(uint2*)&sA[0][row][kq] = make_uint2(*(uint32_t*)&ah01, *(uint32_t*)&ah23);
            *(uint2*)&sA[1][row][kq] = make_uint2(*(uint32_t*)&al01, *(uint32_t*)&al23);

            float4 bv = *(const float4*)(Bexp + (size_t)(n0 + row) * K + k0 + kq);
            __nv_bfloat162 bh01 = __floats2bfloat162_rn(bv.x, bv.y);
            __nv_bfloat162 bh23 = __floats2bfloat162_rn(bv.z, bv.w);
            float2 g01 = __bfloat1622float2(bh01);
            float2 g23 = __bfloat1622float2(bh23);
            __nv_bfloat162 bl01 = __floats2bfloat162_rn(bv.x - g01.x, bv.y - g01.y);
            __nv_bfloat162 bl23 = __floats2bfloat162_rn(bv.z - g23.x, bv.w - g23.y);
            *(uint2*)&sB[0][row][kq] = make_uint2(*(uint32_t*)&bh01, *(uint32_t*)&bh23);
            *(uint2*)&sB[1][row][kq] = make_uint2(*(uint32_t*)&bl01, *(uint32_t*)&bl23);
        }
        __syncthreads();

        // ---- MMA: 2 k-steps of k16 ------------------------------------------
#pragma unroll
        for (int ks = 0; ks < 2; ks++) {
            // A fragments: [mt][plane][4]
            uint32_t aF[2][2][4];
            int arow = (lane & 15);
            int acol = ks * 16 + ((lane >> 4) << 3);
#pragma unroll
            for (int mt = 0; mt < 2; mt++)
#pragma unroll
                for (int pl = 0; pl < 2; pl++) {
                    uint32_t ad = smem_u32(&sA[pl][mbase + mt * 16 + arow][acol]);
                    LDMX4(aF[mt][pl][0], aF[mt][pl][1], aF[mt][pl][2], aF[mt][pl][3], ad);
                }

            // B fragments: process in pairs of n-tiles to limit registers
            int bseg = lane >> 3;            // 0..3
            int bidx = lane & 7;
            int brow_off = (bseg >= 2) ? 8 : 0;
            int bcol = ks * 16 + ((bseg & 1) << 3);
#pragma unroll
            for (int p = 0; p < 4; p++) {    // n-tile pair {2p, 2p+1}
                uint32_t bF[2][2][2];        // [which nt][plane][2]
#pragma unroll
                for (int pl = 0; pl < 2; pl++) {
                    uint32_t r0_, r1_, r2_, r3_;
                    uint32_t bd = smem_u32(
                        &sB[pl][nbase + p * 16 + brow_off + bidx][bcol]);
                    LDMX4(r0_, r1_, r2_, r3_, bd);
                    bF[0][pl][0] = r0_; bF[0][pl][1] = r1_;
                    bF[1][pl][0] = r2_; bF[1][pl][1] = r3_;
                }
#pragma unroll
                for (int mt = 0; mt < 2; mt++)
#pragma unroll
                    for (int w = 0; w < 2; w++) {
                        int nt = 2 * p + w;
                        mma16816(C[mt][nt], aF[mt][0], bF[w][0]); // hi*hi
                        mma16816(C[mt][nt], aF[mt][0], bF[w][1]); // hi*lo
                        mma16816(C[mt][nt], aF[mt][1], bF[w][0]); // lo*hi
                    }
            }
        }
    }

    // ---------------- epilogue ---------------------------------------------
    int g  = lane >> 2;
    int t4 = lane & 3;
    const float* bias = biasAll + (size_t)e * N;

#pragma unroll
    for (int mt = 0; mt < 2; mt++) {
        int rA = r0 + mbase + mt * 16 + g;       // rows rA and rA+8
#pragma unroll
        for (int nt = 0; nt < 8; nt++) {
            int col = n0 + nbase + nt * 8 + t4 * 2;
            float bsv0 = bias[col], bsv1 = bias[col + 1];
            float u0 = C[mt][nt][0] + bsv0;
            float u1 = C[mt][nt][1] + bsv1;
            float u2 = C[mt][nt][2] + bsv0;
            float u3 = C[mt][nt][3] + bsv1;
            if (GELU) {
                float c0 = 0.7978845608028654f * (u0 + 0.044715f * u0 * u0 * u0);
                float c1 = 0.7978845608028654f * (u1 + 0.044715f * u1 * u1 * u1);
                float c2 = 0.7978845608028654f * (u2 + 0.044715f * u2 * u2 * u2);
                float c3 = 0.7978845608028654f * (u3 + 0.044715f * u3 * u3 * u3);
                float v0 = u0 / (1.f + __expf(-2.f * c0));
                float v1 = u1 / (1.f + __expf(-2.f * c1));
                float v2 = u2 / (1.f + __expf(-2.f * c2));
                float v3 = u3 / (1.f + __expf(-2.f * c3));
                if (rA < seg1)
                    *(float2*)&g_h[(size_t)(rA - off0) * N + col] = make_float2(v0, v1);
                if (rA + 8 < seg1)
                    *(float2*)&g_h[(size_t)(rA + 8 - off0) * N + col] = make_float2(v2, v3);
            } else {
                if (rA < seg1) {
                    int tt = g_rows[rA]; float w = g_wpair[rA];
                    atomicAdd(out + (size_t)tt * N + col,     w * u0);
                    atomicAdd(out + (size_t)tt * N + col + 1, w * u1);
                }
                if (rA + 8 < seg1) {
                    int tt = g_rows[rA + 8]; float w = g_wpair[rA + 8];
                    atomicAdd(out + (size_t)tt * N + col,     w * u2);
                    atomicAdd(out + (size_t)tt * N + col + 1, w * u3);
                }
            }
        }
    }
}

// ---------------- launch -----------------------------------------------------
extern "C" void kernel_launch(void* const* d_in, const int* in_sizes, int n_in,
                              void* d_out, int out_size) {
    const float* x    = (const float*)d_in[0];
    const float* semb = (const float*)d_in[1];
    const float* rw   = (const float*)d_in[2];
    const float* rb   = (const float*)d_in[3];
    const float* w1   = (const float*)d_in[4];
    const float* b1   = (const float*)d_in[5];
    const float* w2   = (const float*)d_in[6];
    const float* b2   = (const float*)d_in[7];
    const int*   sidx = (const int*)d_in[8];
    float* out = (float*)d_out;

    zero_kernel<<<1, 32>>>();
    zero_out_kernel<<<(T_TOKENS * DMODEL / 4) / 256, 256>>>(out);
    router_kernel<<<T_TOKENS / 8, 256>>>(x, semb, rw, rb, sidx);
    scan_kernel<<<1, 32>>>();
    build_kernel<<<T_TOKENS / 256, 256>>>();

    // Per-expert chained GEMMs: g_h reused across experts; stream order
    // guarantees GEMM1(e) -> GEMM2(e) -> GEMM1(e+1).
    for (int e = 0; e < NEXP; e++) {
        dim3 g1(HDIM / 128, 64);    // K=1024, N=4096
        moe_gemm_mma<true,  true ><<<g1, 256>>>(x, w1, b1, out, DMODEL, HDIM, e);
        dim3 g2(DMODEL / 128, 64);  // K=4096, N=1024
        moe_gemm_mma<false, false><<<g2, 256>>>(x, w2, b2, out, HDIM, DMODEL, e);
    }
}

// round 13
// speedup vs baseline: 4.7265x; 1.7424x over previous
#include <cuda_runtime.h>
#include <cuda_bf16.h>
#include <math.h>
#include <stdint.h>

#define T_TOKENS 8192
#define DMODEL   1024
#define HDIM     4096
#define NEXP     8
#define NPAIR    16384   // T_TOKENS * TOP_K

// ---------------- scratch (device globals; statics are fine) -----------------
__device__ __nv_bfloat16 g_xs_hi[(size_t)T_TOKENS * DMODEL];
__device__ __nv_bfloat16 g_xs_lo[(size_t)T_TOKENS * DMODEL];
__device__ __nv_bfloat16 g_hs_hi[(size_t)NPAIR * HDIM];
__device__ __nv_bfloat16 g_hs_lo[(size_t)NPAIR * HDIM];
__device__ __nv_bfloat16 g_w1_hi[(size_t)NEXP * HDIM * DMODEL];
__device__ __nv_bfloat16 g_w1_lo[(size_t)NEXP * HDIM * DMODEL];
__device__ __nv_bfloat16 g_w2_hi[(size_t)NEXP * DMODEL * HDIM];
__device__ __nv_bfloat16 g_w2_lo[(size_t)NEXP * DMODEL * HDIM];
__device__ int   g_topk_idx[T_TOKENS * 2];
__device__ float g_topk_w[T_TOKENS * 2];
__device__ int   g_cnt[NEXP];
__device__ int   g_off[NEXP + 1];
__device__ int   g_cur[NEXP];
__device__ int   g_rows[NPAIR];
__device__ float g_wpair[NPAIR];

// ---------------- helpers ----------------------------------------------------
__device__ __forceinline__ uint32_t smem_u32(const void* p) {
    uint32_t a;
    asm("{ .reg .u64 t; cvta.to.shared.u64 t, %1; cvt.u32.u64 %0, t; }"
        : "=r"(a) : "l"(p));
    return a;
}
#define LDMX4(r0, r1, r2, r3, addr) \
    asm volatile("ldmatrix.sync.aligned.m8n8.x4.shared.b16 {%0,%1,%2,%3}, [%4];" \
                 : "=r"(r0), "=r"(r1), "=r"(r2), "=r"(r3) : "r"(addr))

__device__ __forceinline__ void mma16816(float* c, const uint32_t* a,
                                         const uint32_t* b) {
    asm volatile(
        "mma.sync.aligned.m16n8k16.row.col.f32.bf16.bf16.f32 "
        "{%0,%1,%2,%3}, {%4,%5,%6,%7}, {%8,%9}, {%0,%1,%2,%3};"
        : "+f"(c[0]), "+f"(c[1]), "+f"(c[2]), "+f"(c[3])
        : "r"(a[0]), "r"(a[1]), "r"(a[2]), "r"(a[3]), "r"(b[0]), "r"(b[1]));
}
__device__ __forceinline__ void cp16(uint32_t saddr, const void* gaddr, int sz) {
    asm volatile("cp.async.ca.shared.global [%0], [%1], 16, %2;"
                 :: "r"(saddr), "l"(gaddr), "r"(sz));
}
#define CP_COMMIT() asm volatile("cp.async.commit_group;" ::: "memory")
#define CP_WAIT1()  asm volatile("cp.async.wait_group 1;" ::: "memory")
#define CP_WAIT0()  asm volatile("cp.async.wait_group 0;" ::: "memory")

// ---------------- small kernels ---------------------------------------------
__global__ void zero_kernel() {
    int i = threadIdx.x;
    if (i < NEXP) { g_cnt[i] = 0; g_cur[i] = 0; }
}
__global__ void zero_out_kernel(float* __restrict__ out) {
    ((float4*)out)[(size_t)blockIdx.x * blockDim.x + threadIdx.x] =
        make_float4(0.f, 0.f, 0.f, 0.f);
}

// split fp32 -> (bf16 hi, bf16 lo) planes. which: 0=W1, 1=W2, 2=x
__global__ void split_kernel(const float* __restrict__ src, int which, int n4) {
    int i = blockIdx.x * blockDim.x + threadIdx.x;
    if (i >= n4) return;
    __nv_bfloat16* hi = (which == 0) ? g_w1_hi : (which == 1) ? g_w2_hi : g_xs_hi;
    __nv_bfloat16* lo = (which == 0) ? g_w1_lo : (which == 1) ? g_w2_lo : g_xs_lo;
    float4 v = ((const float4*)src)[i];
    __nv_bfloat162 h01 = __floats2bfloat162_rn(v.x, v.y);
    __nv_bfloat162 h23 = __floats2bfloat162_rn(v.z, v.w);
    float2 f01 = __bfloat1622float2(h01);
    float2 f23 = __bfloat1622float2(h23);
    __nv_bfloat162 l01 = __floats2bfloat162_rn(v.x - f01.x, v.y - f01.y);
    __nv_bfloat162 l23 = __floats2bfloat162_rn(v.z - f23.x, v.w - f23.y);
    ((uint2*)hi)[i] = make_uint2(*(uint32_t*)&h01, *(uint32_t*)&h23);
    ((uint2*)lo)[i] = make_uint2(*(uint32_t*)&l01, *(uint32_t*)&l23);
}

__global__ void router_kernel(const float* __restrict__ x,
                              const float* __restrict__ semb,
                              const float* __restrict__ rw,
                              const float* __restrict__ rb,
                              const int*   __restrict__ sidx) {
    int gw   = (blockIdx.x * blockDim.x + threadIdx.x) >> 5;
    int lane = threadIdx.x & 31;
    if (gw >= T_TOKENS) return;
    const float* xr = x + (size_t)gw * DMODEL;
    const float* er = semb + (size_t)(*sidx) * DMODEL;
    float acc[NEXP];
#pragma unroll
    for (int e = 0; e < NEXP; e++) acc[e] = 0.f;
    for (int d = lane; d < DMODEL; d += 32) {
        float v = xr[d] + er[d];
#pragma unroll
        for (int e = 0; e < NEXP; e++) acc[e] += v * rw[e * DMODEL + d];
    }
#pragma unroll
    for (int e = 0; e < NEXP; e++) {
#pragma unroll
        for (int o = 16; o > 0; o >>= 1)
            acc[e] += __shfl_xor_sync(0xffffffffu, acc[e], o);
    }
    if (lane == 0) {
        float b0 = -1e30f, b1 = -1e30f; int i0 = 0, i1 = 0;
#pragma unroll
        for (int e = 0; e < NEXP; e++) {
            float l = acc[e] + rb[e];
            if (l > b0)      { b1 = b0; i1 = i0; b0 = l; i0 = e; }
            else if (l > b1) { b1 = l;  i1 = e; }
        }
        float w0 = 1.f / (1.f + expf(b1 - b0));
        float w1 = 1.f - w0;
        g_topk_idx[2 * gw]     = i0;
        g_topk_idx[2 * gw + 1] = i1;
        g_topk_w[2 * gw]       = w0;
        g_topk_w[2 * gw + 1]   = w1;
        atomicAdd(&g_cnt[i0], 1);
        atomicAdd(&g_cnt[i1], 1);
    }
}

__global__ void scan_kernel() {
    if (threadIdx.x == 0) {
        int s = 0;
        for (int e = 0; e < NEXP; e++) { g_off[e] = s; g_cur[e] = s; s += g_cnt[e]; }
        g_off[NEXP] = s;
    }
}

__global__ void build_kernel() {
    int t = blockIdx.x * blockDim.x + threadIdx.x;
    if (t >= T_TOKENS) return;
#pragma unroll
    for (int k = 0; k < 2; k++) {
        int e = g_topk_idx[2 * t + k];
        int p = atomicAdd(&g_cur[e], 1);
        g_rows[p]  = t;
        g_wpair[p] = g_topk_w[2 * t + k];
    }
}

// ---------------- HMMA grouped GEMM, cp.async double-buffered -----------------
// All operands pre-split to bf16 hi/lo planes; fills are pure 16B cp.async.
// Tile M=128, N=128, BK=32; 8 warps (4Mx2N), warp tile 32x64.
// SMEM stage: 4 planes x 128 rows x 40 halves (80B padded) = 40960 B; 2 stages.
#define PLANE_B   10240
#define STAGE_B   40960
#define GEMM_SMEM 81920

template <bool GATHER, bool GELU>
__global__ __launch_bounds__(256, 2)
void moe_gemm_cp(const float* __restrict__ biasAll,
                 float* __restrict__ out, int K, int N) {
    int e    = blockIdx.z;
    int off0 = g_off[e];
    int seg1 = g_off[e + 1];
    int r0   = off0 + blockIdx.y * 128;
    if (r0 >= seg1) return;
    int n0 = blockIdx.x * 128;

    const __nv_bfloat16* Ahi = GATHER ? g_xs_hi : g_hs_hi;
    const __nv_bfloat16* Alo = GATHER ? g_xs_lo : g_hs_lo;
    const __nv_bfloat16* Whi = (GATHER ? g_w1_hi : g_w2_hi) + (size_t)e * N * K;
    const __nv_bfloat16* Wlo = (GATHER ? g_w1_lo : g_w2_lo) + (size_t)e * N * K;

    extern __shared__ char dsm[];
    uint32_t sbase = smem_u32(dsm);

    int tid   = threadIdx.x;
    int wid   = tid >> 5;
    int lane  = tid & 31;
    int mbase = (wid & 3) * 32;
    int nbase = (wid >> 2) * 64;

    float C[2][8][4];
#pragma unroll
    for (int mt = 0; mt < 2; mt++)
#pragma unroll
        for (int nt = 0; nt < 8; nt++)
#pragma unroll
            for (int q = 0; q < 4; q++) C[mt][nt][q] = 0.f;

    const int KT = K >> 5;

    auto issue = [&](int stage, int kt) {
        int k0 = kt * 32;
        uint32_t sb = sbase + stage * STAGE_B;
#pragma unroll
        for (int i = 0; i < 8; i++) {
            int q   = tid + i * 256;    // 0..2047
            int p   = q >> 9;           // 0 Ahi, 1 Alo, 2 Whi, 3 Wlo
            int cq  = q & 511;
            int row = cq >> 2;
            int ch  = cq & 3;
            uint32_t saddr = sb + p * PLANE_B + row * 80 + ch * 16;
            const __nv_bfloat16* gp;
            int sz = 16;
            if (p < 2) {
                const __nv_bfloat16* plane = p ? Alo : Ahi;
                int r = r0 + row;
                if (r < seg1) {
                    int src = GATHER ? g_rows[r] : r;
                    gp = plane + (size_t)src * K + k0 + ch * 8;
                } else { gp = plane; sz = 0; }     // zero-fill pad rows
            } else {
                const __nv_bfloat16* plane = (p == 2) ? Whi : Wlo;
                gp = plane + (size_t)(n0 + row) * K + k0 + ch * 8;
            }
            cp16(saddr, gp, sz);
        }
        CP_COMMIT();
    };

    issue(0, 0);
    issue(1, 1);

    for (int kt = 0; kt < KT; kt++) {
        int s = kt & 1;
        if (kt < KT - 1) CP_WAIT1(); else CP_WAIT0();
        __syncthreads();

        uint32_t aHiB = sbase + s * STAGE_B;
        uint32_t aLoB = aHiB + PLANE_B;
        uint32_t bHiB = aHiB + 2 * PLANE_B;
        uint32_t bLoB = aHiB + 3 * PLANE_B;

#pragma unroll
        for (int ks = 0; ks < 2; ks++) {
            uint32_t aF[2][2][4];
            int arow  = (lane & 15);
            int acolB = (ks * 16 + ((lane >> 4) << 3)) * 2;
#pragma unroll
            for (int mt = 0; mt < 2; mt++)
#pragma unroll
                for (int pl = 0; pl < 2; pl++) {
                    uint32_t ad = (pl ? aLoB : aHiB) +
                                  (mbase + mt * 16 + arow) * 80 + acolB;
                    LDMX4(aF[mt][pl][0], aF[mt][pl][1], aF[mt][pl][2], aF[mt][pl][3], ad);
                }

            int bseg = lane >> 3;
            int bidx = lane & 7;
            int brow_off = (bseg >= 2) ? 8 : 0;
            int bcolB = (ks * 16 + ((bseg & 1) << 3)) * 2;
#pragma unroll
            for (int p = 0; p < 4; p++) {
                uint32_t bF[2][2][2];
#pragma unroll
                for (int pl = 0; pl < 2; pl++) {
                    uint32_t r0_, r1_, r2_, r3_;
                    uint32_t bd = (pl ? bLoB : bHiB) +
                                  (nbase + p * 16 + brow_off + bidx) * 80 + bcolB;
                    LDMX4(r0_, r1_, r2_, r3_, bd);
                    bF[0][pl][0] = r0_; bF[0][pl][1] = r1_;
                    bF[1][pl][0] = r2_; bF[1][pl][1] = r3_;
                }
#pragma unroll
                for (int mt = 0; mt < 2; mt++)
#pragma unroll
                    for (int w = 0; w < 2; w++) {
                        int nt = 2 * p + w;
                        mma16816(C[mt][nt], aF[mt][0], bF[w][0]); // hi*hi
                        mma16816(C[mt][nt], aF[mt][0], bF[w][1]); // hi*lo
                        mma16816(C[mt][nt], aF[mt][1], bF[w][0]); // lo*hi
                    }
            }
        }
        __syncthreads();
        if (kt + 2 < KT) issue(s, kt + 2);
    }

    // ---------------- epilogue ---------------------------------------------
    int g  = lane >> 2;
    int t4 = lane & 3;
    const float* bias = biasAll + (size_t)e * N;

#pragma unroll
    for (int mt = 0; mt < 2; mt++) {
        int rA = r0 + mbase + mt * 16 + g;       // rows rA and rA+8
#pragma unroll
        for (int nt = 0; nt < 8; nt++) {
            int col = n0 + nbase + nt * 8 + t4 * 2;
            float bsv0 = bias[col], bsv1 = bias[col + 1];
            float u0 = C[mt][nt][0] + bsv0;
            float u1 = C[mt][nt][1] + bsv1;
            float u2 = C[mt][nt][2] + bsv0;
            float u3 = C[mt][nt][3] + bsv1;
            if (GELU) {
                float c0 = 0.7978845608028654f * (u0 + 0.044715f * u0 * u0 * u0);
                float c1 = 0.7978845608028654f * (u1 + 0.044715f * u1 * u1 * u1);
                float c2 = 0.7978845608028654f * (u2 + 0.044715f * u2 * u2 * u2);
                float c3 = 0.7978845608028654f * (u3 + 0.044715f * u3 * u3 * u3);
                float v0 = u0 / (1.f + __expf(-2.f * c0));
                float v1 = u1 / (1.f + __expf(-2.f * c1));
                float v2 = u2 / (1.f + __expf(-2.f * c2));
                float v3 = u3 / (1.f + __expf(-2.f * c3));
                if (rA < seg1) {
                    size_t base = (size_t)rA * N + col;
                    __nv_bfloat162 h2 = __floats2bfloat162_rn(v0, v1);
                    float2 hf = __bfloat1622float2(h2);
                    __nv_bfloat162 l2 = __floats2bfloat162_rn(v0 - hf.x, v1 - hf.y);
                    *(uint32_t*)&g_hs_hi[base] = *(uint32_t*)&h2;
                    *(uint32_t*)&g_hs_lo[base] = *(uint32_t*)&l2;
                }
                if (rA + 8 < seg1) {
                    size_t base = (size_t)(rA + 8) * N + col;
                    __nv_bfloat162 h2 = __floats2bfloat162_rn(v2, v3);
                    float2 hf = __bfloat1622float2(h2);
                    __nv_bfloat162 l2 = __floats2bfloat162_rn(v2 - hf.x, v3 - hf.y);
                    *(uint32_t*)&g_hs_hi[base] = *(uint32_t*)&h2;
                    *(uint32_t*)&g_hs_lo[base] = *(uint32_t*)&l2;
                }
            } else {
                if (rA < seg1) {
                    int tt = g_rows[rA]; float w = g_wpair[rA];
                    atomicAdd(out + (size_t)tt * N + col,     w * u0);
                    atomicAdd(out + (size_t)tt * N + col + 1, w * u1);
                }
                if (rA + 8 < seg1) {
                    int tt = g_rows[rA + 8]; float w = g_wpair[rA + 8];
                    atomicAdd(out + (size_t)tt * N + col,     w * u2);
                    atomicAdd(out + (size_t)tt * N + col + 1, w * u3);
                }
            }
        }
    }
}

// ---------------- launch -----------------------------------------------------
extern "C" void kernel_launch(void* const* d_in, const int* in_sizes, int n_in,
                              void* d_out, int out_size) {
    const float* x    = (const float*)d_in[0];
    const float* semb = (const float*)d_in[1];
    const float* rw   = (const float*)d_in[2];
    const float* rb   = (const float*)d_in[3];
    const float* w1   = (const float*)d_in[4];
    const float* b1   = (const float*)d_in[5];
    const float* w2   = (const float*)d_in[6];
    const float* b2   = (const float*)d_in[7];
    const int*   sidx = (const int*)d_in[8];
    float* out = (float*)d_out;

    cudaFuncSetAttribute(moe_gemm_cp<true,  true >,
                         cudaFuncAttributeMaxDynamicSharedMemorySize, GEMM_SMEM);
    cudaFuncSetAttribute(moe_gemm_cp<false, false>,
                         cudaFuncAttributeMaxDynamicSharedMemorySize, GEMM_SMEM);

    zero_kernel<<<1, 32>>>();
    zero_out_kernel<<<(T_TOKENS * DMODEL / 4) / 256, 256>>>(out);

    // pre-split all GEMM operands into bf16 hi/lo planes
    int wN4 = NEXP * HDIM * DMODEL / 4;
    int xN4 = T_TOKENS * DMODEL / 4;
    split_kernel<<<wN4 / 256, 256>>>(w1, 0, wN4);
    split_kernel<<<wN4 / 256, 256>>>(w2, 1, wN4);
    split_kernel<<<xN4 / 256, 256>>>(x,  2, xN4);

    router_kernel<<<T_TOKENS / 8, 256>>>(x, semb, rw, rb, sidx);
    scan_kernel<<<1, 32>>>();
    build_kernel<<<T_TOKENS / 256, 256>>>();

    // GEMM1: hs = split(gelu(x @ W1^T + b1)), all experts in one launch
    dim3 g1(HDIM / 128, 64, NEXP);
    moe_gemm_cp<true,  true ><<<g1, 256, GEMM_SMEM>>>(b1, out, DMODEL, HDIM);
    // GEMM2: out += w * (h @ W2^T + b2), all experts in one launch
    dim3 g2(DMODEL / 128, 64, NEXP);
    moe_gemm_cp<false, false><<<g2, 256, GEMM_SMEM>>>(b2, out, HDIM, DMODEL);
}

// round 14
// speedup vs baseline: 7.0652x; 1.4948x over previous
#include <cuda_runtime.h>
#include <cuda_fp16.h>
#include <math.h>
#include <stdint.h>

#define T_TOKENS 8192
#define DMODEL   1024
#define HDIM     4096
#define NEXP     8
#define NPAIR    16384   // T_TOKENS * TOP_K

// ---------------- scratch (device globals; statics are fine) -----------------
__device__ __half g_xs_hi[(size_t)T_TOKENS * DMODEL];
__device__ __half g_xs_lo[(size_t)T_TOKENS * DMODEL];
__device__ __half g_hs_hi[(size_t)NPAIR * HDIM];
__device__ __half g_hs_lo[(size_t)NPAIR * HDIM];
__device__ __half g_w1_h[(size_t)NEXP * HDIM * DMODEL];
__device__ __half g_w2_h[(size_t)NEXP * DMODEL * HDIM];
__device__ int   g_topk_idx[T_TOKENS * 2];
__device__ float g_topk_w[T_TOKENS * 2];
__device__ int   g_cnt[NEXP];
__device__ int   g_off[NEXP + 1];
__device__ int   g_cur[NEXP];
__device__ int   g_rows[NPAIR];
__device__ float g_wpair[NPAIR];

// ---------------- helpers ----------------------------------------------------
__device__ __forceinline__ uint32_t smem_u32(const void* p) {
    uint32_t a;
    asm("{ .reg .u64 t; cvta.to.shared.u64 t, %1; cvt.u32.u64 %0, t; }"
        : "=r"(a) : "l"(p));
    return a;
}
#define LDMX4(r0, r1, r2, r3, addr) \
    asm volatile("ldmatrix.sync.aligned.m8n8.x4.shared.b16 {%0,%1,%2,%3}, [%4];" \
                 : "=r"(r0), "=r"(r1), "=r"(r2), "=r"(r3) : "r"(addr))

__device__ __forceinline__ void mma16816(float* c, const uint32_t* a,
                                         const uint32_t* b) {
    asm volatile(
        "mma.sync.aligned.m16n8k16.row.col.f32.f16.f16.f32 "
        "{%0,%1,%2,%3}, {%4,%5,%6,%7}, {%8,%9}, {%0,%1,%2,%3};"
        : "+f"(c[0]), "+f"(c[1]), "+f"(c[2]), "+f"(c[3])
        : "r"(a[0]), "r"(a[1]), "r"(a[2]), "r"(a[3]), "r"(b[0]), "r"(b[1]));
}
__device__ __forceinline__ void cp16(uint32_t saddr, const void* gaddr, int sz) {
    asm volatile("cp.async.ca.shared.global [%0], [%1], 16, %2;"
                 :: "r"(saddr), "l"(gaddr), "r"(sz));
}
#define CP_COMMIT() asm volatile("cp.async.commit_group;" ::: "memory")
#define CP_WAIT1()  asm volatile("cp.async.wait_group 1;" ::: "memory")
#define CP_WAIT0()  asm volatile("cp.async.wait_group 0;" ::: "memory")

// ---------------- small kernels ---------------------------------------------
__global__ void zero_kernel() {
    int i = threadIdx.x;
    if (i < NEXP) { g_cnt[i] = 0; g_cur[i] = 0; }
}
__global__ void zero_out_kernel(float* __restrict__ out) {
    ((float4*)out)[(size_t)blockIdx.x * blockDim.x + threadIdx.x] =
        make_float4(0.f, 0.f, 0.f, 0.f);
}

// fp32 -> fp16 planes. which: 0=W1 (hi only), 1=W2 (hi only), 2=x (hi+lo)
__global__ void split_kernel(const float* __restrict__ src, int which, int n4) {
    int i = blockIdx.x * blockDim.x + threadIdx.x;
    if (i >= n4) return;
    float4 v = ((const float4*)src)[i];
    __half2 h01 = __floats2half2_rn(v.x, v.y);
    __half2 h23 = __floats2half2_rn(v.z, v.w);
    if (which == 0) {
        ((uint2*)g_w1_h)[i] = make_uint2(*(uint32_t*)&h01, *(uint32_t*)&h23);
    } else if (which == 1) {
        ((uint2*)g_w2_h)[i] = make_uint2(*(uint32_t*)&h01, *(uint32_t*)&h23);
    } else {
        float2 f01 = __half22float2(h01);
        float2 f23 = __half22float2(h23);
        __half2 l01 = __floats2half2_rn(v.x - f01.x, v.y - f01.y);
        __half2 l23 = __floats2half2_rn(v.z - f23.x, v.w - f23.y);
        ((uint2*)g_xs_hi)[i] = make_uint2(*(uint32_t*)&h01, *(uint32_t*)&h23);
        ((uint2*)g_xs_lo)[i] = make_uint2(*(uint32_t*)&l01, *(uint32_t*)&l23);
    }
}

__global__ void router_kernel(const float* __restrict__ x,
                              const float* __restrict__ semb,
                              const float* __restrict__ rw,
                              const float* __restrict__ rb,
                              const int*   __restrict__ sidx) {
    int gw   = (blockIdx.x * blockDim.x + threadIdx.x) >> 5;
    int lane = threadIdx.x & 31;
    if (gw >= T_TOKENS) return;
    const float* xr = x + (size_t)gw * DMODEL;
    const float* er = semb + (size_t)(*sidx) * DMODEL;
    float acc[NEXP];
#pragma unroll
    for (int e = 0; e < NEXP; e++) acc[e] = 0.f;
    for (int d = lane; d < DMODEL; d += 32) {
        float v = xr[d] + er[d];
#pragma unroll
        for (int e = 0; e < NEXP; e++) acc[e] += v * rw[e * DMODEL + d];
    }
#pragma unroll
    for (int e = 0; e < NEXP; e++) {
#pragma unroll
        for (int o = 16; o > 0; o >>= 1)
            acc[e] += __shfl_xor_sync(0xffffffffu, acc[e], o);
    }
    if (lane == 0) {
        float b0 = -1e30f, b1 = -1e30f; int i0 = 0, i1 = 0;
#pragma unroll
        for (int e = 0; e < NEXP; e++) {
            float l = acc[e] + rb[e];
            if (l > b0)      { b1 = b0; i1 = i0; b0 = l; i0 = e; }
            else if (l > b1) { b1 = l;  i1 = e; }
        }
        float w0 = 1.f / (1.f + expf(b1 - b0));
        float w1 = 1.f - w0;
        g_topk_idx[2 * gw]     = i0;
        g_topk_idx[2 * gw + 1] = i1;
        g_topk_w[2 * gw]       = w0;
        g_topk_w[2 * gw + 1]   = w1;
        atomicAdd(&g_cnt[i0], 1);
        atomicAdd(&g_cnt[i1], 1);
    }
}

__global__ void scan_kernel() {
    if (threadIdx.x == 0) {
        int s = 0;
        for (int e = 0; e < NEXP; e++) { g_off[e] = s; g_cur[e] = s; s += g_cnt[e]; }
        g_off[NEXP] = s;
    }
}

__global__ void build_kernel() {
    int t = blockIdx.x * blockDim.x + threadIdx.x;
    if (t >= T_TOKENS) return;
#pragma unroll
    for (int k = 0; k < 2; k++) {
        int e = g_topk_idx[2 * t + k];
        int p = atomicAdd(&g_cur[e], 1);
        g_rows[p]  = t;
        g_wpair[p] = g_topk_w[2 * t + k];
    }
}

// ---------------- HMMA grouped GEMM, cp.async double-buffered -----------------
// fp32 emulated asymmetrically: A = ah + al (fp16 2-term), W = wh (fp16 single).
// 2 MMAs per output: ah*wh + al*wh. Dominant error = fp16(W) rounding ~1.4e-4.
// Tile M=128, N=128, BK=32; 8 warps (4Mx2N), warp tile 32x64.
// SMEM stage: 3 planes x 128 rows x 40 halves (80B padded) = 30720 B; 2 stages.
#define PLANE_B   10240
#define STAGE_B   30720
#define GEMM_SMEM 61440

template <bool GATHER, bool GELU>
__global__ __launch_bounds__(256, 2)
void moe_gemm_cp(const float* __restrict__ biasAll,
                 float* __restrict__ out, int K, int N) {
    int e    = blockIdx.z;
    int off0 = g_off[e];
    int seg1 = g_off[e + 1];
    int r0   = off0 + blockIdx.y * 128;
    if (r0 >= seg1) return;
    int n0 = blockIdx.x * 128;

    const __half* Ahi = GATHER ? g_xs_hi : g_hs_hi;
    const __half* Alo = GATHER ? g_xs_lo : g_hs_lo;
    const __half* Wh  = (GATHER ? g_w1_h : g_w2_h) + (size_t)e * N * K;

    extern __shared__ char dsm[];
    uint32_t sbase = smem_u32(dsm);

    int tid   = threadIdx.x;
    int wid   = tid >> 5;
    int lane  = tid & 31;
    int mbase = (wid & 3) * 32;
    int nbase = (wid >> 2) * 64;

    float C[2][8][4];
#pragma unroll
    for (int mt = 0; mt < 2; mt++)
#pragma unroll
        for (int nt = 0; nt < 8; nt++)
#pragma unroll
            for (int q = 0; q < 4; q++) C[mt][nt][q] = 0.f;

    const int KT = K >> 5;

    auto issue = [&](int stage, int kt) {
        int k0 = kt * 32;
        uint32_t sb = sbase + stage * STAGE_B;
#pragma unroll
        for (int i = 0; i < 6; i++) {
            int q   = tid + i * 256;    // 0..1535
            int p   = q >> 9;           // 0 Ahi, 1 Alo, 2 Wh
            int cq  = q & 511;
            int row = cq >> 2;
            int ch  = cq & 3;
            uint32_t saddr = sb + p * PLANE_B + row * 80 + ch * 16;
            const __half* gp;
            int sz = 16;
            if (p < 2) {
                const __half* plane = p ? Alo : Ahi;
                int r = r0 + row;
                if (r < seg1) {
                    int src = GATHER ? g_rows[r] : r;
                    gp = plane + (size_t)src * K + k0 + ch * 8;
                } else { gp = plane; sz = 0; }     // zero-fill pad rows
            } else {
                gp = Wh + (size_t)(n0 + row) * K + k0 + ch * 8;
            }
            cp16(saddr, gp, sz);
        }
        CP_COMMIT();
    };

    issue(0, 0);
    issue(1, 1);

    for (int kt = 0; kt < KT; kt++) {
        int s = kt & 1;
        if (kt < KT - 1) CP_WAIT1(); else CP_WAIT0();
        __syncthreads();

        uint32_t aHiB = sbase + s * STAGE_B;
        uint32_t aLoB = aHiB + PLANE_B;
        uint32_t bB   = aHiB + 2 * PLANE_B;

#pragma unroll
        for (int ks = 0; ks < 2; ks++) {
            uint32_t aF[2][2][4];
            int arow  = (lane & 15);
            int acolB = (ks * 16 + ((lane >> 4) << 3)) * 2;
#pragma unroll
            for (int mt = 0; mt < 2; mt++)
#pragma unroll
                for (int pl = 0; pl < 2; pl++) {
                    uint32_t ad = (pl ? aLoB : aHiB) +
                                  (mbase + mt * 16 + arow) * 80 + acolB;
                    LDMX4(aF[mt][pl][0], aF[mt][pl][1], aF[mt][pl][2], aF[mt][pl][3], ad);
                }

            int bseg = lane >> 3;
            int bidx = lane & 7;
            int brow_off = (bseg >= 2) ? 8 : 0;
            int bcolB = (ks * 16 + ((bseg & 1) << 3)) * 2;
#pragma unroll
            for (int p = 0; p < 4; p++) {
                uint32_t bF[2][2];
                {
                    uint32_t r0_, r1_, r2_, r3_;
                    uint32_t bd = bB +
                                  (nbase + p * 16 + brow_off + bidx) * 80 + bcolB;
                    LDMX4(r0_, r1_, r2_, r3_, bd);
                    bF[0][0] = r0_; bF[0][1] = r1_;
                    bF[1][0] = r2_; bF[1][1] = r3_;
                }
#pragma unroll
                for (int mt = 0; mt < 2; mt++)
#pragma unroll
                    for (int w = 0; w < 2; w++) {
                        int nt = 2 * p + w;
                        mma16816(C[mt][nt], aF[mt][0], bF[w]);  // hi * w
                        mma16816(C[mt][nt], aF[mt][1], bF[w]);  // lo * w
                    }
            }
        }
        __syncthreads();
        if (kt + 2 < KT) issue(s, kt + 2);
    }

    // ---------------- epilogue ---------------------------------------------
    int g  = lane >> 2;
    int t4 = lane & 3;
    const float* bias = biasAll + (size_t)e * N;

#pragma unroll
    for (int mt = 0; mt < 2; mt++) {
        int rA = r0 + mbase + mt * 16 + g;       // rows rA and rA+8
#pragma unroll
        for (int nt = 0; nt < 8; nt++) {
            int col = n0 + nbase + nt * 8 + t4 * 2;
            float bsv0 = bias[col], bsv1 = bias[col + 1];
            float u0 = C[mt][nt][0] + bsv0;
            float u1 = C[mt][nt][1] + bsv1;
            float u2 = C[mt][nt][2] + bsv0;
            float u3 = C[mt][nt][3] + bsv1;
            if (GELU) {
                float c0 = 0.7978845608028654f * (u0 + 0.044715f * u0 * u0 * u0);
                float c1 = 0.7978845608028654f * (u1 + 0.044715f * u1 * u1 * u1);
                float c2 = 0.7978845608028654f * (u2 + 0.044715f * u2 * u2 * u2);
                float c3 = 0.7978845608028654f * (u3 + 0.044715f * u3 * u3 * u3);
                float v0 = u0 / (1.f + __expf(-2.f * c0));
                float v1 = u1 / (1.f + __expf(-2.f * c1));
                float v2 = u2 / (1.f + __expf(-2.f * c2));
                float v3 = u3 / (1.f + __expf(-2.f * c3));
                if (rA < seg1) {
                    size_t base = (size_t)rA * N + col;
                    __half2 h2 = __floats2half2_rn(v0, v1);
                    float2 hf = __half22float2(h2);
                    __half2 l2 = __floats2half2_rn(v0 - hf.x, v1 - hf.y);
                    *(uint32_t*)&g_hs_hi[base] = *(uint32_t*)&h2;
                    *(uint32_t*)&g_hs_lo[base] = *(uint32_t*)&l2;
                }
                if (rA + 8 < seg1) {
                    size_t base = (size_t)(rA + 8) * N + col;
                    __half2 h2 = __floats2half2_rn(v2, v3);
                    float2 hf = __half22float2(h2);
                    __half2 l2 = __floats2half2_rn(v2 - hf.x, v3 - hf.y);
                    *(uint32_t*)&g_hs_hi[base] = *(uint32_t*)&h2;
                    *(uint32_t*)&g_hs_lo[base] = *(uint32_t*)&l2;
                }
            } else {
                if (rA < seg1) {
                    int tt = g_rows[rA]; float w = g_wpair[rA];
                    atomicAdd(out + (size_t)tt * N + col,     w * u0);
                    atomicAdd(out + (size_t)tt * N + col + 1, w * u1);
                }
                if (rA + 8 < seg1) {
                    int tt = g_rows[rA + 8]; float w = g_wpair[rA + 8];
                    atomicAdd(out + (size_t)tt * N + col,     w * u2);
                    atomicAdd(out + (size_t)tt * N + col + 1, w * u3);
                }
            }
        }
    }
}

// ---------------- launch -----------------------------------------------------
extern "C" void kernel_launch(void* const* d_in, const int* in_sizes, int n_in,
                              void* d_out, int out_size) {
    const float* x    = (const float*)d_in[0];
    const float* semb = (const float*)d_in[1];
    const float* rw   = (const float*)d_in[2];
    const float* rb   = (const float*)d_in[3];
    const float* w1   = (const float*)d_in[4];
    const float* b1   = (const float*)d_in[5];
    const float* w2   = (const float*)d_in[6];
    const float* b2   = (const float*)d_in[7];
    const int*   sidx = (const int*)d_in[8];
    float* out = (float*)d_out;

    cudaFuncSetAttribute(moe_gemm_cp<true,  true >,
                         cudaFuncAttributeMaxDynamicSharedMemorySize, GEMM_SMEM);
    cudaFuncSetAttribute(moe_gemm_cp<false, false>,
                         cudaFuncAttributeMaxDynamicSharedMemorySize, GEMM_SMEM);

    zero_kernel<<<1, 32>>>();
    zero_out_kernel<<<(T_TOKENS * DMODEL / 4) / 256, 256>>>(out);

    // pre-split GEMM operands into fp16 planes (W: hi only; x: hi+lo)
    int wN4 = NEXP * HDIM * DMODEL / 4;
    int xN4 = T_TOKENS * DMODEL / 4;
    split_kernel<<<wN4 / 256, 256>>>(w1, 0, wN4);
    split_kernel<<<wN4 / 256, 256>>>(w2, 1, wN4);
    split_kernel<<<xN4 / 256, 256>>>(x,  2, xN4);

    router_kernel<<<T_TOKENS / 8, 256>>>(x, semb, rw, rb, sidx);
    scan_kernel<<<1, 32>>>();
    build_kernel<<<T_TOKENS / 256, 256>>>();

    // GEMM1: hs = split(gelu(x @ W1^T + b1)), all experts in one launch
    dim3 g1(HDIM / 128, 64, NEXP);
    moe_gemm_cp<true,  true ><<<g1, 256, GEMM_SMEM>>>(b1, out, DMODEL, HDIM);
    // GEMM2: out += w * (h @ W2^T + b2), all experts in one launch
    dim3 g2(DMODEL / 128, 64, NEXP);
    moe_gemm_cp<false, false><<<g2, 256, GEMM_SMEM>>>(b2, out, HDIM, DMODEL);
}